// round 9
// baseline (speedup 1.0000x reference)
#include <cuda_runtime.h>
#include <cstdint>

// out[b,t,:] = tok_weight[x[b,t],:] + pos_weight[t,:]
// B=4, T=4096, E=512 fp32.
//
// R9 experiment: kill cross-CTA L1tex-queue spread. Per B300 model,
// spr_max = 1.10 + 25*(oe*MLP_p1 - 16)/T_CTA; all prior variants had
// front-batched LDG counts (MLP_p1) of 7-13 -> predicted ~1.8-2x CTA
// completion spread at oe~8. This version fully serializes the per-warp
// chain (x_i -> gather_i -> store_i), so MLP_p1 ~= 2 (pos + x0 only).
// Latency is hidden by warp count (8192 warps, ~55/SM), not per-warp ILP.
// 256-bit accesses (8 floats/lane) keep instruction count minimal.

struct U64x4 { unsigned long long v0, v1, v2, v3; };

__device__ __forceinline__ U64x4 ldg256(const float* p) {
    U64x4 r;
    asm volatile("ld.global.nc.v4.b64 {%0,%1,%2,%3}, [%4];"
                 : "=l"(r.v0), "=l"(r.v1), "=l"(r.v2), "=l"(r.v3) : "l"(p));
    return r;
}

__device__ __forceinline__ void stg256(float* p, U64x4 r) {
    asm volatile("st.global.v4.b64 [%0], {%1,%2,%3,%4};"
                 :: "l"(p), "l"(r.v0), "l"(r.v1), "l"(r.v2), "l"(r.v3)
                 : "memory");
}

__device__ __forceinline__ unsigned long long addx2(unsigned long long a,
                                                    unsigned long long b) {
    unsigned long long r;
    asm("add.rn.f32x2 %0, %1, %2;" : "=l"(r) : "l"(a), "l"(b));
    return r;
}

__device__ __forceinline__ U64x4 add4(U64x4 a, U64x4 p) {
    U64x4 r;
    r.v0 = addx2(a.v0, p.v0);
    r.v1 = addx2(a.v1, p.v1);
    r.v2 = addx2(a.v2, p.v2);
    r.v3 = addx2(a.v3, p.v3);
    return r;
}

__global__ void __launch_bounds__(256) pos_embed_kernel(
    const int* __restrict__ x,            // [4*T]
    const float* __restrict__ tok_w,      // [VOCAB, 512]
    const float* __restrict__ pos_w,      // [T, 512]
    float* __restrict__ out,              // [4*T, 512]
    int T)                                // 4096
{
    const int wid_global = blockIdx.x * (blockDim.x >> 5) + (threadIdx.x >> 5);
    const int t    = wid_global >> 1;          // time step
    const int half = wid_global & 1;           // which 256-float half of row
    if (t >= T) return;
    const int lane = threadIdx.x & 31;
    const int col  = half * 256 + lane * 8;    // float offset within row

    const float* tw = tok_w + col;
    float* o = out + (long long)t * 512 + col;
    const long long bstride = (long long)T * 512;

    // Front batch = exactly 2 loads (pos + x0); everything after is a
    // serial dependence chain -> MLP_p1 ~= 2, below the Q_th=16 knee.
    const U64x4 p = ldg256(pos_w + (long long)t * 512 + col);

    int tok0 = __ldg(&x[t]);
    U64x4 a = ldg256(tw + (long long)tok0 * 512);
    stg256(o, add4(a, p));

    int tok1 = __ldg(&x[t + T]);
    U64x4 b = ldg256(tw + (long long)tok1 * 512);
    stg256(o + bstride, add4(b, p));

    int tok2 = __ldg(&x[t + 2 * T]);
    U64x4 c = ldg256(tw + (long long)tok2 * 512);
    stg256(o + 2 * bstride, add4(c, p));

    int tok3 = __ldg(&x[t + 3 * T]);
    U64x4 d = ldg256(tw + (long long)tok3 * 512);
    stg256(o + 3 * bstride, add4(d, p));
}

extern "C" void kernel_launch(void* const* d_in, const int* in_sizes, int n_in,
                              void* d_out, int out_size) {
    const int*   x     = (const int*)d_in[0];
    const float* tok_w = (const float*)d_in[1];
    const float* pos_w = (const float*)d_in[2];
    float*       out   = (float*)d_out;

    const int T = 4096;                       // fixed problem shape (B=4)
    const int total_warps = T * 2;            // (t, half) = 8192
    const int threads = 256;                  // 8 warps/block
    const int warps_per_blk = threads / 32;
    int blocks = (total_warps + warps_per_blk - 1) / warps_per_blk;  // 1024

    pos_embed_kernel<<<blocks, threads>>>(x, tok_w, pos_w, out, T);
}